// round 14
// baseline (speedup 1.0000x reference)
#include <cuda_runtime.h>
#include <cuda_bf16.h>
#include <cuda_fp16.h>
#include <cstdint>

#define N_NODESC 20000
#define N_EDGESC 320000
#define IN_FC    256
#define OUT_FC   64
#define HEADSC   4
#define ALPHAC   0.1f
#define CAPC     64   // bucket capacity per node (Poisson(16); max ~45)

// ---------------- scratch (static device globals; no allocation) ----------------
// g_STh layout: [dir][node][head][64] fp16
__device__ __half g_STh[2 * N_NODESC * HEADSC * OUT_FC];   // ~20.5 MB
__device__ float g_P1[N_NODESC * 8];   // [node][z]; z = dir*4+head (vs a1)
__device__ float g_P2[N_NODESC * 8];   // same vs a2
__device__ int g_degT[N_NODESC], g_degS[N_NODESC];
__device__ int g_nbrT[N_NODESC * CAPC];
__device__ int g_nbrS[N_NODESC * CAPC];
// fp16 operands: X (both dirs) [dir][node][k], W^T per z [z][n][k]
__device__ __half g_Xf[2 * N_NODESC * IN_FC];
__device__ __half g_Btf[8 * OUT_FC * IN_FC];

// ---------------- mma helpers ----------------
__device__ __forceinline__ uint32_t smem_u32(const void* p) {
    uint32_t a;
    asm("{ .reg .u64 t; cvta.to.shared.u64 t, %1; cvt.u32.u64 %0, t; }" : "=r"(a) : "l"(p));
    return a;
}
// SW64 swizzle for 64-byte rows: conflict-free 8-row x 16B ldmatrix reads
#define SWZ64(o) ((o) ^ (((o) >> 3) & 0x30))

#define LDSM_X4(r, addr) \
    asm volatile("ldmatrix.sync.aligned.m8n8.x4.shared.b16 {%0,%1,%2,%3}, [%4];" \
        : "=r"((r)[0]), "=r"((r)[1]), "=r"((r)[2]), "=r"((r)[3]) : "r"(addr))

#define MMA_F16(d, a, b0, b1) \
    asm volatile("mma.sync.aligned.m16n8k16.row.col.f32.f16.f16.f32 " \
        "{%0,%1,%2,%3},{%4,%5,%6,%7},{%8,%9},{%0,%1,%2,%3};" \
        : "+f"((d)[0]), "+f"((d)[1]), "+f"((d)[2]), "+f"((d)[3]) \
        : "r"((a)[0]), "r"((a)[1]), "r"((a)[2]), "r"((a)[3]), "r"(b0), "r"(b1))

#define CP_ASYNC_16(dst, src, zf) \
    asm volatile("cp.async.cg.shared.global [%0], [%1], 16, %2;" \
        :: "r"(dst), "l"(src), "r"(zf))
#define CP_COMMIT() asm volatile("cp.async.commit_group;")
#define CP_WAIT2()  asm volatile("cp.async.wait_group 2;")
#define CP_WAIT1()  asm volatile("cp.async.wait_group 1;")
#define CP_WAIT0()  asm volatile("cp.async.wait_group 0;")

// ---------------- kernel 0: zero degree counters ----------------
__global__ void zero_kernel() {
    int i = blockIdx.x * blockDim.x + threadIdx.x;
    if (i < N_NODESC) { g_degT[i] = 0; g_degS[i] = 0; }
}

// ---------------- kernel 1: bucket-CSR fill ----------------
__global__ void fill_kernel(const int* __restrict__ src, const int* __restrict__ tgt) {
    int e = blockIdx.x * blockDim.x + threadIdx.x;
    if (e >= N_EDGESC) return;
    int t = tgt[e], s = src[e];
    int st = atomicAdd(&g_degT[t], 1);
    g_nbrT[(t << 6) + st] = s;
    int ss = atomicAdd(&g_degS[s], 1);
    g_nbrS[(s << 6) + ss] = t;
}

// ---------------- kernel 2: fused fp16 conversion (X + transposed W) ----------------
__global__ void conv_kernel(const float* __restrict__ x1, const float* __restrict__ x2,
                            const float* __restrict__ Ws, const float* __restrict__ Wt) {
    const int NX = 2 * N_NODESC * IN_FC / 8;           // X groups of 8 floats
    const int NW = 8 * OUT_FC * IN_FC / 4;             // W groups of 4 floats
    int i = blockIdx.x * blockDim.x + threadIdx.x;
    if (i < NX) {
        const int half = NX / 2;
        const float* X = (i < half) ? x1 : x2;
        int li = (i < half) ? i : i - half;
        const float4* src = (const float4*)(X + (size_t)li * 8);
        float4 v0 = src[0], v1 = src[1];
        __half2 h0 = __floats2half2_rn(v0.x, v0.y);
        __half2 h1 = __floats2half2_rn(v0.z, v0.w);
        __half2 h2 = __floats2half2_rn(v1.x, v1.y);
        __half2 h3 = __floats2half2_rn(v1.z, v1.w);
        uint4 o;
        o.x = *(uint32_t*)&h0; o.y = *(uint32_t*)&h1;
        o.z = *(uint32_t*)&h2; o.w = *(uint32_t*)&h3;
        *(uint4*)(g_Xf + (size_t)i * 8) = o;
    } else {
        int k = i - NX;
        if (k >= NW) return;
        int k0 = (k & 63) * 4;     // 64 k-groups per (z, n)
        int zn = k >> 6;
        int z = zn >> 6, n = zn & 63;
        int head = z & 3, dir = z >> 2;
        const float* W = (dir ? Wt : Ws) + head * IN_FC * OUT_FC;
        float a[4];
#pragma unroll
        for (int kk = 0; kk < 4; kk++) a[kk] = __ldg(&W[(size_t)(k0 + kk) * OUT_FC + n]);
        __half2 h0 = __floats2half2_rn(a[0], a[1]);
        __half2 h1 = __floats2half2_rn(a[2], a[3]);
        uint2 o;
        o.x = *(uint32_t*)&h0; o.y = *(uint32_t*)&h1;
        *(uint2*)(g_Btf + ((size_t)z * OUT_FC + n) * IN_FC + k0) = o;
    }
}

// ---------------- kernel 3: HMMA fp16 GEMM, 3-stage cp.async pipeline ----------------
// grid (157, 8), block 256 = 4 m-warps x 2 n-warps. Tile 128x64, K-chunk 32.
// 3 smem stages: two chunks in flight behind the one being computed.
__global__ void __launch_bounds__(256) gemm_mma_kernel(
    const float* __restrict__ a1, const float* __restrict__ a2)
{
    __shared__ __align__(16) __half sA[3][128 * 32];  // [stage][m][k], SW64 rows
    __shared__ __align__(16) __half sB[3][64 * 32];   // [stage][n][k], SW64 rows
    __shared__ float sP1[128], sP2[128];
    __shared__ float sW1[64], sW2[64];

    int z = blockIdx.y, head = z & 3, dir = z >> 2;
    int m0 = blockIdx.x * 128;
    int tid = threadIdx.x, wid = tid >> 5, lane = tid & 31;
    int wm = wid & 3, wn = wid >> 2;

    if (tid < 128) { sP1[tid] = 0.0f; sP2[tid] = 0.0f; }
    if (tid < 64) {
        int ao = head * 2 * OUT_FC + dir * OUT_FC + tid;
        sW1[tid] = a1[ao];
        sW2[tid] = a2[ao];
    }

    uint32_t bA = smem_u32(sA), bB = smem_u32(sB);

    int arow = tid >> 1, ahalf = tid & 1;
    int am = m0 + arow;
    bool aok = am < N_NODESC;
    int amsafe = aok ? am : 0;
    int azf = aok ? 16 : 0;
    const __half* xf = g_Xf + ((size_t)dir * N_NODESC + amsafe) * IN_FC + ahalf * 16;
    int brow = (tid >> 1) & 63;
    const __half* bf = g_Btf + ((size_t)z * OUT_FC + brow) * IN_FC + ahalf * 16;

    uint32_t aso[2], bso[2];
#pragma unroll
    for (int cg = 0; cg < 2; cg++) {
        aso[cg] = SWZ64((uint32_t)(arow * 64 + ahalf * 32 + cg * 16));
        bso[cg] = SWZ64((uint32_t)(brow * 64 + ahalf * 32 + cg * 16));
    }

    float acc[2][4][4];
#pragma unroll
    for (int t = 0; t < 2; t++)
#pragma unroll
        for (int na = 0; na < 4; na++)
#pragma unroll
            for (int r = 0; r < 4; r++) acc[t][na][r] = 0.0f;

    // prologue: stage chunks 0 and 1 into buffers 0 and 1 (one group each)
#pragma unroll
    for (int s = 0; s < 2; s++) {
        int kc = s * 32;
        uint32_t abase = bA + s * 8192;
        uint32_t bbase = bB + s * 4096;
#pragma unroll
        for (int cg = 0; cg < 2; cg++)
            CP_ASYNC_16(abase + aso[cg], xf + kc + cg * 8, azf);
        if (tid < 128)
#pragma unroll
            for (int cg = 0; cg < 2; cg++)
                CP_ASYNC_16(bbase + bso[cg], bf + kc + cg * 8, 16);
        CP_COMMIT();
    }

    for (int c = 0; c < 8; c++) {
        int cur = c % 3;
        // stage chunk c+2 into buffer (c+2)%3 (last used by chunk c-1, already synced)
        if (c + 2 < 8) {
            int nxt = (c + 2) % 3;
            int kc = (c + 2) * 32;
            uint32_t abase = bA + nxt * 8192;
            uint32_t bbase = bB + nxt * 4096;
#pragma unroll
            for (int cg = 0; cg < 2; cg++)
                CP_ASYNC_16(abase + aso[cg], xf + kc + cg * 8, azf);
            if (tid < 128)
#pragma unroll
                for (int cg = 0; cg < 2; cg++)
                    CP_ASYNC_16(bbase + bso[cg], bf + kc + cg * 8, 16);
            CP_COMMIT();
            CP_WAIT2();   // chunk c complete; c+1, c+2 in flight
        } else if (c + 1 < 8) {
            CP_WAIT1();   // chunk c complete; c+1 in flight
        } else {
            CP_WAIT0();
        }
        __syncthreads();

        uint32_t cA = bA + cur * 8192;
        uint32_t cB = bB + cur * 4096;
#pragma unroll
        for (int ks = 0; ks < 2; ks++) {
            int k0 = ks * 16;
            uint32_t af[2][4];
#pragma unroll
            for (int t = 0; t < 2; t++) {
                int rowA = wm * 32 + t * 16 + (lane & 7) + ((lane >> 3) & 1) * 8;
                int kk = k0 + ((lane >> 4) & 1) * 8;
                uint32_t off = SWZ64((uint32_t)(rowA * 64 + kk * 2));
                LDSM_X4(af[t], cA + off);
            }
            uint32_t bfr[2][4];
#pragma unroll
            for (int p = 0; p < 2; p++) {
                int rowB = wn * 32 + p * 16 + (lane & 7) + ((lane >> 4) & 1) * 8;
                int kk = k0 + ((lane >> 3) & 1) * 8;
                uint32_t off = SWZ64((uint32_t)(rowB * 64 + kk * 2));
                LDSM_X4(bfr[p], cB + off);
            }
#pragma unroll
            for (int t = 0; t < 2; t++) {
#pragma unroll
                for (int na = 0; na < 4; na++) {
                    int p = na >> 1, s = (na & 1) * 2;
                    MMA_F16(acc[t][na], af[t], bfr[p][s], bfr[p][s + 1]);
                }
            }
        }
        __syncthreads();   // all warps done reading buf[cur] before restage
    }

    // epilogue: D fragment -> fp16 rows + projection partials
    int g = lane >> 2, tig = lane & 3;
#pragma unroll
    for (int t = 0; t < 2; t++) {
#pragma unroll
        for (int half = 0; half < 2; half++) {
            int rl = wm * 32 + t * 16 + g + half * 8;
            int m = m0 + rl;
            if (m >= N_NODESC) continue;
            __half* o = &g_STh[(((size_t)dir * N_NODESC + m) * HEADSC + head) * OUT_FC];
            float d1 = 0.f, d2 = 0.f;
#pragma unroll
            for (int na = 0; na < 4; na++) {
                int col = wn * 32 + na * 8 + tig * 2;
                float v0 = acc[t][na][half * 2 + 0];
                float v1 = acc[t][na][half * 2 + 1];
                *(__half2*)&o[col] = __floats2half2_rn(v0, v1);
                d1 += v0 * sW1[col] + v1 * sW1[col + 1];
                d2 += v0 * sW2[col] + v1 * sW2[col + 1];
            }
            atomicAdd(&sP1[rl], d1);
            atomicAdd(&sP2[rl], d2);
        }
    }
    __syncthreads();
    if (tid < 128) {
        int m = m0 + tid;
        if (m < N_NODESC) {
            g_P1[m * 8 + z] = sP1[tid];
            g_P2[m * 8 + z] = sP2[tid];
        }
    }
}

// ---------------- kernel 4: fused softmax-weight + gather aggregation + ELU ------
__global__ void __launch_bounds__(256) agg_kernel(float* __restrict__ out) {
    __shared__ float sAl[8][CAPC * HEADSC];   // per-warp alpha tile: [slot][head]

    int wslot = threadIdx.x >> 5;
    int gw = (blockIdx.x * 256 + threadIdx.x) >> 5;
    int lane = threadIdx.x & 31;
    int node = gw >> 1, dir = gw & 1;
    if (node >= N_NODESC) return;

    int deg;
    const int* __restrict__ nbr;
    const float* __restrict__ P;
    const __half* __restrict__ rows;
    int ooff, poff;
    if (dir == 0) {  // h_st: node=src, weights from P2, gather T rows
        deg = g_degS[node]; nbr = g_nbrS + (node << 6);
        P = g_P2; ooff = 0; poff = 4;
        rows = g_STh + (size_t)N_NODESC * (HEADSC * OUT_FC);
    } else {         // h_ts: node=tgt, weights from P1, gather S rows
        deg = g_degT[node]; nbr = g_nbrT + (node << 6);
        P = g_P1; ooff = 4; poff = 0;
        rows = g_STh;
    }

    // ---- phase 1: alphas ----
    int sh = lane & 3;   // head
    int se = lane >> 2;  // slot within chunk of 8
    float own = __ldg(&P[node * 8 + ooff + sh]);

    float wreg[8];
    float denp = 0.0f;
#pragma unroll
    for (int it = 0; it < 8; it++) {
        int j = it * 8 + se;
        float w = 0.0f;
        if (j < deg) {
            int nb = __ldg(&nbr[j]);
            float e = own + __ldg(&P[nb * 8 + poff + sh]);
            e = fmaxf(e, ALPHAC * e);   // leaky_relu (alpha>0)
            w = __expf(e);
        }
        wreg[it] = w;
        denp += w;
    }
    denp += __shfl_xor_sync(0xFFFFFFFFu, denp, 4);
    denp += __shfl_xor_sync(0xFFFFFFFFu, denp, 8);
    denp += __shfl_xor_sync(0xFFFFFFFFu, denp, 16);
    float inv = (denp > 0.0f) ? (1.0f / denp) : 0.0f;
#pragma unroll
    for (int it = 0; it < 8; it++)
        sAl[wslot][((it * 8 + se) << 2) + sh] = wreg[it] * inv;
    __syncwarp();

    // ---- phase 2: gather + accumulate ----
    int fh = lane >> 3;
    int laneoff = fh * OUT_FC + (lane & 7) * 8;

    float a0 = 0.f, a1v = 0.f, a2v = 0.f, a3 = 0.f;
    float a4 = 0.f, a5 = 0.f, a6 = 0.f, a7 = 0.f;

#pragma unroll 8
    for (int j = 0; j < deg; j++) {
        int nbb = __ldg(&nbr[j]);
        float al = sAl[wslot][(j << 2) + fh];
        const __half* base = rows + nbb * (HEADSC * OUT_FC) + laneoff;
        uint4 q = *(const uint4*)(base);
        float2 v0 = __half22float2(*(const __half2*)&q.x);
        float2 v1 = __half22float2(*(const __half2*)&q.y);
        float2 v2 = __half22float2(*(const __half2*)&q.z);
        float2 v3 = __half22float2(*(const __half2*)&q.w);
        a0 += al * v0.x; a1v += al * v0.y;
        a2v += al * v1.x; a3 += al * v1.y;
        a4 += al * v2.x; a5 += al * v2.y;
        a6 += al * v3.x; a7 += al * v3.y;
    }

    float r0 = (a0 > 0.f) ? a0 : expm1f(a0);
    float r1 = (a1v > 0.f) ? a1v : expm1f(a1v);
    float r2 = (a2v > 0.f) ? a2v : expm1f(a2v);
    float r3 = (a3 > 0.f) ? a3 : expm1f(a3);
    float r4 = (a4 > 0.f) ? a4 : expm1f(a4);
    float r5 = (a5 > 0.f) ? a5 : expm1f(a5);
    float r6 = (a6 > 0.f) ? a6 : expm1f(a6);
    float r7 = (a7 > 0.f) ? a7 : expm1f(a7);

    float* o = out + ((size_t)(dir ? N_NODESC : 0) + node) * (HEADSC * OUT_FC) + laneoff;
    *(float4*)(o)     = make_float4(r0, r1, r2, r3);
    *(float4*)(o + 4) = make_float4(r4, r5, r6, r7);
}

// ---------------- launch ----------------
extern "C" void kernel_launch(void* const* d_in, const int* in_sizes, int n_in,
                              void* d_out, int out_size) {
    const float* x1 = (const float*)d_in[0];
    const float* x2 = (const float*)d_in[1];
    const float* Ws = (const float*)d_in[2];
    const float* Wt = (const float*)d_in[3];
    const float* a1 = (const float*)d_in[4];
    const float* a2 = (const float*)d_in[5];
    const int* tgt  = (const int*)d_in[6];
    const int* src  = (const int*)d_in[7];
    float* out = (float*)d_out;

    // side stream + events for capture-legal fork/join (created on the first,
    // uncaptured, correctness call; reused thereafter — resources, not work)
    static cudaStream_t s2 = nullptr;
    static cudaEvent_t evFork = nullptr, evJoin = nullptr;
    if (s2 == nullptr) {
        cudaStreamCreateWithFlags(&s2, cudaStreamNonBlocking);
        cudaEventCreateWithFlags(&evFork, cudaEventDisableTiming);
        cudaEventCreateWithFlags(&evJoin, cudaEventDisableTiming);
    }

    // fork: CSR chain (zero -> fill) runs concurrently with conv + gemm
    cudaEventRecord(evFork, 0);
    cudaStreamWaitEvent(s2, evFork, 0);
    zero_kernel<<<(N_NODESC + 255) / 256, 256, 0, s2>>>();
    fill_kernel<<<(N_EDGESC + 255) / 256, 256, 0, s2>>>(src, tgt);
    cudaEventRecord(evJoin, s2);

    const int NCONV = 2 * N_NODESC * IN_FC / 8 + 8 * OUT_FC * IN_FC / 4;
    conv_kernel<<<(NCONV + 255) / 256, 256>>>(x1, x2, Ws, Wt);

    dim3 gg((N_NODESC + 127) / 128, 8);
    gemm_mma_kernel<<<gg, 256>>>(a1, a2);

    // join: agg needs both the CSR and the projections/rows
    cudaStreamWaitEvent(0, evJoin, 0);
    agg_kernel<<<(N_NODESC * 2 * 32 + 255) / 256, 256>>>(out);
}

// round 15
// speedup vs baseline: 1.0506x; 1.0506x over previous
#include <cuda_runtime.h>
#include <cuda_bf16.h>
#include <cuda_fp16.h>
#include <cstdint>

#define N_NODESC 20000
#define N_EDGESC 320000
#define IN_FC    256
#define OUT_FC   64
#define HEADSC   4
#define ALPHAC   0.1f
#define CAPC     64   // bucket capacity per node (Poisson(16); max ~45)

// ---------------- scratch (static device globals; no allocation) ----------------
// g_STh layout: [dir][node][head][64] fp16
__device__ __half g_STh[2 * N_NODESC * HEADSC * OUT_FC];   // ~20.5 MB
__device__ float g_P1[N_NODESC * 8];   // [node][z]; z = dir*4+head (vs a1)
__device__ float g_P2[N_NODESC * 8];   // same vs a2
__device__ int g_degT[N_NODESC], g_degS[N_NODESC];
__device__ int g_nbrT[N_NODESC * CAPC];
__device__ int g_nbrS[N_NODESC * CAPC];
// fp16 operands: X (both dirs) [dir][node][k], W^T per z [z][n][k]
__device__ __half g_Xf[2 * N_NODESC * IN_FC];
__device__ __half g_Btf[8 * OUT_FC * IN_FC];

// ---------------- mma helpers ----------------
__device__ __forceinline__ uint32_t smem_u32(const void* p) {
    uint32_t a;
    asm("{ .reg .u64 t; cvta.to.shared.u64 t, %1; cvt.u32.u64 %0, t; }" : "=r"(a) : "l"(p));
    return a;
}
// SW64 swizzle for 64-byte rows: conflict-free 8-row x 16B ldmatrix reads
#define SWZ64(o) ((o) ^ (((o) >> 3) & 0x30))

#define LDSM_X4(r, addr) \
    asm volatile("ldmatrix.sync.aligned.m8n8.x4.shared.b16 {%0,%1,%2,%3}, [%4];" \
        : "=r"((r)[0]), "=r"((r)[1]), "=r"((r)[2]), "=r"((r)[3]) : "r"(addr))

#define MMA_F16(d, a, b0, b1) \
    asm volatile("mma.sync.aligned.m16n8k16.row.col.f32.f16.f16.f32 " \
        "{%0,%1,%2,%3},{%4,%5,%6,%7},{%8,%9},{%0,%1,%2,%3};" \
        : "+f"((d)[0]), "+f"((d)[1]), "+f"((d)[2]), "+f"((d)[3]) \
        : "r"((a)[0]), "r"((a)[1]), "r"((a)[2]), "r"((a)[3]), "r"(b0), "r"(b1))

#define CP_ASYNC_16(dst, src, zf) \
    asm volatile("cp.async.cg.shared.global [%0], [%1], 16, %2;" \
        :: "r"(dst), "l"(src), "r"(zf))
#define CP_COMMIT() asm volatile("cp.async.commit_group;")
#define CP_WAIT1()  asm volatile("cp.async.wait_group 1;")
#define CP_WAIT0()  asm volatile("cp.async.wait_group 0;")

// ---------------- kernel 0: zero degree counters ----------------
__global__ void zero_kernel() {
    int i = blockIdx.x * blockDim.x + threadIdx.x;
    if (i < N_NODESC) { g_degT[i] = 0; g_degS[i] = 0; }
}

// ---------------- kernel 1: bucket-CSR fill ----------------
__global__ void fill_kernel(const int* __restrict__ src, const int* __restrict__ tgt) {
    int e = blockIdx.x * blockDim.x + threadIdx.x;
    if (e >= N_EDGESC) return;
    int t = tgt[e], s = src[e];
    int st = atomicAdd(&g_degT[t], 1);
    g_nbrT[(t << 6) + st] = s;
    int ss = atomicAdd(&g_degS[s], 1);
    g_nbrS[(s << 6) + ss] = t;
}

// ---------------- kernel 2: fused fp16 conversion (X + transposed W) ----------------
__global__ void conv_kernel(const float* __restrict__ x1, const float* __restrict__ x2,
                            const float* __restrict__ Ws, const float* __restrict__ Wt) {
    const int NX = 2 * N_NODESC * IN_FC / 8;           // X groups of 8 floats
    const int NW = 8 * OUT_FC * IN_FC / 4;             // W groups of 4 floats
    int i = blockIdx.x * blockDim.x + threadIdx.x;
    if (i < NX) {
        const int half = NX / 2;
        const float* X = (i < half) ? x1 : x2;
        int li = (i < half) ? i : i - half;
        const float4* src = (const float4*)(X + (size_t)li * 8);
        float4 v0 = src[0], v1 = src[1];
        __half2 h0 = __floats2half2_rn(v0.x, v0.y);
        __half2 h1 = __floats2half2_rn(v0.z, v0.w);
        __half2 h2 = __floats2half2_rn(v1.x, v1.y);
        __half2 h3 = __floats2half2_rn(v1.z, v1.w);
        uint4 o;
        o.x = *(uint32_t*)&h0; o.y = *(uint32_t*)&h1;
        o.z = *(uint32_t*)&h2; o.w = *(uint32_t*)&h3;
        *(uint4*)(g_Xf + (size_t)i * 8) = o;
    } else {
        int k = i - NX;
        if (k >= NW) return;
        int k0 = (k & 63) * 4;     // 64 k-groups per (z, n)
        int zn = k >> 6;
        int z = zn >> 6, n = zn & 63;
        int head = z & 3, dir = z >> 2;
        const float* W = (dir ? Wt : Ws) + head * IN_FC * OUT_FC;
        float a[4];
#pragma unroll
        for (int kk = 0; kk < 4; kk++) a[kk] = __ldg(&W[(size_t)(k0 + kk) * OUT_FC + n]);
        __half2 h0 = __floats2half2_rn(a[0], a[1]);
        __half2 h1 = __floats2half2_rn(a[2], a[3]);
        uint2 o;
        o.x = *(uint32_t*)&h0; o.y = *(uint32_t*)&h1;
        *(uint2*)(g_Btf + ((size_t)z * OUT_FC + n) * IN_FC + k0) = o;
    }
}

// ---------------- kernel 3: HMMA fp16 GEMM, cp.async double-buffered ----------------
// (measured-best 2-stage pipeline from round 13)
__global__ void __launch_bounds__(256) gemm_mma_kernel(
    const float* __restrict__ a1, const float* __restrict__ a2)
{
    __shared__ __align__(16) __half sA[2][128 * 32];  // [stage][m][k], SW64 rows
    __shared__ __align__(16) __half sB[2][64 * 32];   // [stage][n][k], SW64 rows
    __shared__ float sP1[128], sP2[128];
    __shared__ float sW1[64], sW2[64];

    int z = blockIdx.y, head = z & 3, dir = z >> 2;
    int m0 = blockIdx.x * 128;
    int tid = threadIdx.x, wid = tid >> 5, lane = tid & 31;
    int wm = wid & 3, wn = wid >> 2;

    if (tid < 128) { sP1[tid] = 0.0f; sP2[tid] = 0.0f; }
    if (tid < 64) {
        int ao = head * 2 * OUT_FC + dir * OUT_FC + tid;
        sW1[tid] = a1[ao];
        sW2[tid] = a2[ao];
    }

    uint32_t bA = smem_u32(sA), bB = smem_u32(sB);

    int arow = tid >> 1, ahalf = tid & 1;
    int am = m0 + arow;
    bool aok = am < N_NODESC;
    int amsafe = aok ? am : 0;
    int azf = aok ? 16 : 0;
    const __half* xf = g_Xf + ((size_t)dir * N_NODESC + amsafe) * IN_FC + ahalf * 16;
    int brow = (tid >> 1) & 63;
    const __half* bf = g_Btf + ((size_t)z * OUT_FC + brow) * IN_FC + ahalf * 16;

    uint32_t aso[2], bso[2];
#pragma unroll
    for (int cg = 0; cg < 2; cg++) {
        aso[cg] = SWZ64((uint32_t)(arow * 64 + ahalf * 32 + cg * 16));
        bso[cg] = SWZ64((uint32_t)(brow * 64 + ahalf * 32 + cg * 16));
    }

    float acc[2][4][4];
#pragma unroll
    for (int t = 0; t < 2; t++)
#pragma unroll
        for (int na = 0; na < 4; na++)
#pragma unroll
            for (int r = 0; r < 4; r++) acc[t][na][r] = 0.0f;

    // prologue: stage chunk 0 into buffer 0
#pragma unroll
    for (int cg = 0; cg < 2; cg++)
        CP_ASYNC_16(bA + aso[cg], xf + cg * 8, azf);
    if (tid < 128)
#pragma unroll
        for (int cg = 0; cg < 2; cg++)
            CP_ASYNC_16(bB + bso[cg], bf + cg * 8, 16);
    CP_COMMIT();

    for (int c = 0; c < 8; c++) {
        int cur = c & 1;
        // stage chunk c+1 into the other buffer
        if (c + 1 < 8) {
            int kc = (c + 1) * 32;
            uint32_t abase = bA + (cur ^ 1) * 8192;
            uint32_t bbase = bB + (cur ^ 1) * 4096;
#pragma unroll
            for (int cg = 0; cg < 2; cg++)
                CP_ASYNC_16(abase + aso[cg], xf + kc + cg * 8, azf);
            if (tid < 128)
#pragma unroll
                for (int cg = 0; cg < 2; cg++)
                    CP_ASYNC_16(bbase + bso[cg], bf + kc + cg * 8, 16);
            CP_COMMIT();
            CP_WAIT1();   // chunk c's group complete; c+1 in flight
        } else {
            CP_WAIT0();
        }
        __syncthreads();

        uint32_t cA = bA + cur * 8192;
        uint32_t cB = bB + cur * 4096;
#pragma unroll
        for (int ks = 0; ks < 2; ks++) {
            int k0 = ks * 16;
            uint32_t af[2][4];
#pragma unroll
            for (int t = 0; t < 2; t++) {
                int rowA = wm * 32 + t * 16 + (lane & 7) + ((lane >> 3) & 1) * 8;
                int kk = k0 + ((lane >> 4) & 1) * 8;
                uint32_t off = SWZ64((uint32_t)(rowA * 64 + kk * 2));
                LDSM_X4(af[t], cA + off);
            }
            uint32_t bfr[2][4];
#pragma unroll
            for (int p = 0; p < 2; p++) {
                int rowB = wn * 32 + p * 16 + (lane & 7) + ((lane >> 4) & 1) * 8;
                int kk = k0 + ((lane >> 3) & 1) * 8;
                uint32_t off = SWZ64((uint32_t)(rowB * 64 + kk * 2));
                LDSM_X4(bfr[p], cB + off);
            }
#pragma unroll
            for (int t = 0; t < 2; t++) {
#pragma unroll
                for (int na = 0; na < 4; na++) {
                    int p = na >> 1, s = (na & 1) * 2;
                    MMA_F16(acc[t][na], af[t], bfr[p][s], bfr[p][s + 1]);
                }
            }
        }
        __syncthreads();   // everyone done reading buf[cur] before it is re-staged
    }

    // epilogue: D fragment -> fp16 rows + projection partials
    int g = lane >> 2, tig = lane & 3;
#pragma unroll
    for (int t = 0; t < 2; t++) {
#pragma unroll
        for (int half = 0; half < 2; half++) {
            int rl = wm * 32 + t * 16 + g + half * 8;
            int m = m0 + rl;
            if (m >= N_NODESC) continue;
            __half* o = &g_STh[(((size_t)dir * N_NODESC + m) * HEADSC + head) * OUT_FC];
            float d1 = 0.f, d2 = 0.f;
#pragma unroll
            for (int na = 0; na < 4; na++) {
                int col = wn * 32 + na * 8 + tig * 2;
                float v0 = acc[t][na][half * 2 + 0];
                float v1 = acc[t][na][half * 2 + 1];
                *(__half2*)&o[col] = __floats2half2_rn(v0, v1);
                d1 += v0 * sW1[col] + v1 * sW1[col + 1];
                d2 += v0 * sW2[col] + v1 * sW2[col + 1];
            }
            atomicAdd(&sP1[rl], d1);
            atomicAdd(&sP2[rl], d2);
        }
    }
    __syncthreads();
    if (tid < 128) {
        int m = m0 + tid;
        if (m < N_NODESC) {
            g_P1[m * 8 + z] = sP1[tid];
            g_P2[m * 8 + z] = sP2[tid];
        }
    }
}

// ---------------- kernel 4: fused softmax-weight + gather aggregation + ELU ------
// Phase 1 also stashes neighbor indices in smem, so phase 2's address chain is
// LDS(29cy) -> LDG.128 instead of LDG(~300cy) -> LDG.128: full MLP on gathers.
__global__ void __launch_bounds__(256) agg_kernel(float* __restrict__ out) {
    __shared__ float sAl[8][CAPC * HEADSC];   // per-warp alpha tile: [slot][head]
    __shared__ int   sNb[8][CAPC];            // per-warp neighbor indices

    int wslot = threadIdx.x >> 5;
    int gw = (blockIdx.x * 256 + threadIdx.x) >> 5;
    int lane = threadIdx.x & 31;
    int node = gw >> 1, dir = gw & 1;
    if (node >= N_NODESC) return;

    int deg;
    const int* __restrict__ nbr;
    const float* __restrict__ P;
    const __half* __restrict__ rows;
    int ooff, poff;
    if (dir == 0) {  // h_st: node=src, weights from P2, gather T rows
        deg = g_degS[node]; nbr = g_nbrS + (node << 6);
        P = g_P2; ooff = 0; poff = 4;
        rows = g_STh + (size_t)N_NODESC * (HEADSC * OUT_FC);
    } else {         // h_ts: node=tgt, weights from P1, gather S rows
        deg = g_degT[node]; nbr = g_nbrT + (node << 6);
        P = g_P1; ooff = 4; poff = 0;
        rows = g_STh;
    }

    // ---- phase 1: alphas + neighbor stash ----
    int sh = lane & 3;   // head
    int se = lane >> 2;  // slot within chunk of 8
    float own = __ldg(&P[node * 8 + ooff + sh]);

    float wreg[8];
    float denp = 0.0f;
#pragma unroll
    for (int it = 0; it < 8; it++) {
        int j = it * 8 + se;
        float w = 0.0f;
        if (j < deg) {
            int nb = __ldg(&nbr[j]);
            if (sh == 0) sNb[wslot][j] = nb;
            float e = own + __ldg(&P[nb * 8 + poff + sh]);
            e = fmaxf(e, ALPHAC * e);   // leaky_relu (alpha>0)
            w = __expf(e);
        }
        wreg[it] = w;
        denp += w;
    }
    denp += __shfl_xor_sync(0xFFFFFFFFu, denp, 4);
    denp += __shfl_xor_sync(0xFFFFFFFFu, denp, 8);
    denp += __shfl_xor_sync(0xFFFFFFFFu, denp, 16);
    float inv = (denp > 0.0f) ? (1.0f / denp) : 0.0f;
#pragma unroll
    for (int it = 0; it < 8; it++)
        sAl[wslot][((it * 8 + se) << 2) + sh] = wreg[it] * inv;
    __syncwarp();

    // ---- phase 2: gather + accumulate (smem-fed addresses) ----
    int fh = lane >> 3;
    int laneoff = fh * OUT_FC + (lane & 7) * 8;

    float a0 = 0.f, a1v = 0.f, a2v = 0.f, a3 = 0.f;
    float a4 = 0.f, a5 = 0.f, a6 = 0.f, a7 = 0.f;

#pragma unroll 8
    for (int j = 0; j < deg; j++) {
        int nbb = sNb[wslot][j];
        float al = sAl[wslot][(j << 2) + fh];
        const __half* base = rows + nbb * (HEADSC * OUT_FC) + laneoff;
        uint4 q = *(const uint4*)(base);
        float2 v0 = __half22float2(*(const __half2*)&q.x);
        float2 v1 = __half22float2(*(const __half2*)&q.y);
        float2 v2 = __half22float2(*(const __half2*)&q.z);
        float2 v3 = __half22float2(*(const __half2*)&q.w);
        a0 += al * v0.x; a1v += al * v0.y;
        a2v += al * v1.x; a3 += al * v1.y;
        a4 += al * v2.x; a5 += al * v2.y;
        a6 += al * v3.x; a7 += al * v3.y;
    }

    float r0 = (a0 > 0.f) ? a0 : expm1f(a0);
    float r1 = (a1v > 0.f) ? a1v : expm1f(a1v);
    float r2 = (a2v > 0.f) ? a2v : expm1f(a2v);
    float r3 = (a3 > 0.f) ? a3 : expm1f(a3);
    float r4 = (a4 > 0.f) ? a4 : expm1f(a4);
    float r5 = (a5 > 0.f) ? a5 : expm1f(a5);
    float r6 = (a6 > 0.f) ? a6 : expm1f(a6);
    float r7 = (a7 > 0.f) ? a7 : expm1f(a7);

    float* o = out + ((size_t)(dir ? N_NODESC : 0) + node) * (HEADSC * OUT_FC) + laneoff;
    *(float4*)(o)     = make_float4(r0, r1, r2, r3);
    *(float4*)(o + 4) = make_float4(r4, r5, r6, r7);
}

// ---------------- launch ----------------
extern "C" void kernel_launch(void* const* d_in, const int* in_sizes, int n_in,
                              void* d_out, int out_size) {
    const float* x1 = (const float*)d_in[0];
    const float* x2 = (const float*)d_in[1];
    const float* Ws = (const float*)d_in[2];
    const float* Wt = (const float*)d_in[3];
    const float* a1 = (const float*)d_in[4];
    const float* a2 = (const float*)d_in[5];
    const int* tgt  = (const int*)d_in[6];
    const int* src  = (const int*)d_in[7];
    float* out = (float*)d_out;

    // side stream + events for capture-legal fork/join (created on the first,
    // uncaptured, correctness call; reused thereafter — resources, not work)
    static cudaStream_t s2 = nullptr;
    static cudaEvent_t evFork = nullptr, evJoin = nullptr;
    if (s2 == nullptr) {
        cudaStreamCreateWithFlags(&s2, cudaStreamNonBlocking);
        cudaEventCreateWithFlags(&evFork, cudaEventDisableTiming);
        cudaEventCreateWithFlags(&evJoin, cudaEventDisableTiming);
    }

    // fork: CSR chain (zero -> fill) runs concurrently with conv + gemm
    cudaEventRecord(evFork, 0);
    cudaStreamWaitEvent(s2, evFork, 0);
    zero_kernel<<<(N_NODESC + 255) / 256, 256, 0, s2>>>();
    fill_kernel<<<(N_EDGESC + 255) / 256, 256, 0, s2>>>(src, tgt);
    cudaEventRecord(evJoin, s2);

    const int NCONV = 2 * N_NODESC * IN_FC / 8 + 8 * OUT_FC * IN_FC / 4;
    conv_kernel<<<(NCONV + 255) / 256, 256>>>(x1, x2, Ws, Wt);

    dim3 gg((N_NODESC + 127) / 128, 8);
    gemm_mma_kernel<<<gg, 256>>>(a1, a2);

    // join: agg needs both the CSR and the projections/rows
    cudaStreamWaitEvent(0, evJoin, 0);
    agg_kernel<<<(N_NODESC * 2 * 32 + 255) / 256, 256>>>(out);
}